// round 3
// baseline (speedup 1.0000x reference)
#include <cuda_runtime.h>
#include <math.h>

// ---------------------------------------------------------------------------
// BCEDecorrelatedLoss = bce_mean + 0.1 * distance_corr(outputs, event, wnorm)
//
// Validated decomposition (R2, rel_err 8.6e-6):
//   With normalized weights w (sum w = N), p=|xi-xj|, q=|yi-yj|:
//     asum[i]=sum_j w_j p ; bsum[i]=sum_j w_j q ; t[i]=sum_j w_j p q
//     a0 = sum_i w_i asum_i / N^2
//     S_AA = 2N sum(w x^2) - 2(sum w x)^2 - 2N sum(w (asum/N)^2 ... ) etc.
//     S_AB = T - 2/N sum(w asum bsum) + a0 b0 N^2,  T = sum w_i t_i
//     disco = S_AB / sqrt(S_AA S_BB)
//
// Key: asum/bsum/t are LINEAR in raw weights -> the O(N^2) pass needs no
// preprocessing; normalization (scale = N / sum w_raw) applied in finalize.
// Two launches: [pairwise O(N^2)] -> [finalize O(N), also re-zeros state].
// ---------------------------------------------------------------------------

#define MAXN  8192
#define CT    256   // threads per block
#define ITEMS 4     // i-rows per thread
#define CJT   256   // j-tile per block

// zero-initialized at module load; finalize re-zeros after each launch
__device__ double g_asum[MAXN];
__device__ double g_bsum[MAXN];
__device__ double g_t[MAXN];

// ---- block reductions ------------------------------------------------------
__device__ __forceinline__ float blockReduceF(float v) {
    __shared__ float s[32];
    int lane = threadIdx.x & 31, wid = threadIdx.x >> 5;
    #pragma unroll
    for (int o = 16; o; o >>= 1) v += __shfl_down_sync(0xffffffffu, v, o);
    if (lane == 0) s[wid] = v;
    __syncthreads();
    int nw = blockDim.x >> 5;
    float r = (threadIdx.x < nw) ? s[threadIdx.x] : 0.0f;
    if (wid == 0) {
        #pragma unroll
        for (int o = 16; o; o >>= 1) r += __shfl_down_sync(0xffffffffu, r, o);
        if (lane == 0) s[0] = r;
    }
    __syncthreads();
    float out = s[0];
    __syncthreads();
    return out;
}

__device__ __forceinline__ double blockReduceD(double v) {
    __shared__ double s[32];
    int lane = threadIdx.x & 31, wid = threadIdx.x >> 5;
    #pragma unroll
    for (int o = 16; o; o >>= 1) v += __shfl_down_sync(0xffffffffu, v, o);
    if (lane == 0) s[wid] = v;
    __syncthreads();
    int nw = blockDim.x >> 5;
    double r = (threadIdx.x < nw) ? s[threadIdx.x] : 0.0;
    if (wid == 0) {
        #pragma unroll
        for (int o = 16; o; o >>= 1) r += __shfl_down_sync(0xffffffffu, r, o);
        if (lane == 0) s[0] = r;
    }
    __syncthreads();
    double out = s[0];
    __syncthreads();
    return out;
}

// ---------------------------------------------------------------------------
// kPair: fused O(N^2) pass with RAW weights.
// grid (n/(CT*ITEMS), n/CJT), CT threads. Scalar fp32, float4 j-tile.
// ---------------------------------------------------------------------------
__global__ void __launch_bounds__(CT) kPair(const float* __restrict__ x,
                                            const float* __restrict__ y,
                                            const float* __restrict__ w,
                                            int n) {
    __shared__ __align__(16) float4 tile[CJT];
    int tid = threadIdx.x;

    {   // j tile: {x_j, y_j, w_j, 0}
        int j = blockIdx.y * CJT + tid;
        tile[tid] = make_float4(x[j], y[j], w[j], 0.0f);
    }

    float xi[ITEMS], yi[ITEMS];
    float sa[ITEMS], sb[ITEMS], st[ITEMS];
    int ibase = blockIdx.x * (CT * ITEMS) + tid;
    #pragma unroll
    for (int k = 0; k < ITEMS; ++k) {
        int i = ibase + k * CT;
        xi[k] = x[i]; yi[k] = y[i];
        sa[k] = 0.0f; sb[k] = 0.0f; st[k] = 0.0f;
    }
    __syncthreads();

    #pragma unroll 8
    for (int t = 0; t < CJT; ++t) {
        float4 v = tile[t];            // one LDS.128 serves 4 pairs
        #pragma unroll
        for (int k = 0; k < ITEMS; ++k) {
            float dx  = xi[k] - v.x;
            float dy  = yi[k] - v.y;
            float adx = fabsf(dx);
            float ady = fabsf(dy);
            sa[k] = fmaf(adx, v.z, sa[k]);
            sb[k] = fmaf(ady, v.z, sb[k]);
            st[k] = fmaf(adx * ady, v.z, st[k]);
        }
    }

    #pragma unroll
    for (int k = 0; k < ITEMS; ++k) {
        int i = ibase + k * CT;
        atomicAdd(&g_asum[i], (double)sa[k]);
        atomicAdd(&g_bsum[i], (double)sb[k]);
        atomicAdd(&g_t[i],    (double)st[k]);
    }
}

// ---------------------------------------------------------------------------
// kFinal (1 block, 1024 thr): sumw, BCE, weighted sums (double), disco, output.
// Re-zeros g_asum/g_bsum/g_t for the next graph replay.
// ---------------------------------------------------------------------------
__global__ void kFinal(const float* __restrict__ outputs,
                       const float* __restrict__ labels,
                       const float* __restrict__ event,
                       const float* __restrict__ weights,
                       float* __restrict__ out, int n, int out_size) {
    int tid = threadIdx.x;

    // phase 1: sum of raw weights + BCE mean
    float sw = 0.0f, sb = 0.0f;
    for (int i = tid; i < n; i += blockDim.x) {
        float xv = outputs[i], yv = labels[i], wv = weights[i];
        sw += wv;
        float sp = fmaxf(xv, 0.0f) + log1pf(expf(-fabsf(xv)));  // logaddexp(0,x)
        sb += (sp - xv * yv) * wv;
    }
    float swt = blockReduceF(sw);
    float sbt = blockReduceF(sb);
    double scale = (double)n / (double)swt;
    float bce = sbt / (float)n;

    // phase 2: weighted sums in double (normalized on the fly), re-zero state
    double s1 = 0, s2 = 0, s3 = 0, s4 = 0, s5 = 0;
    double s6 = 0, s7 = 0, s8 = 0, s9 = 0, s10 = 0;
    for (int i = tid; i < n; i += blockDim.x) {
        double wn = scale * (double)weights[i];       // normalized w_i
        double as = scale * g_asum[i];                // normalized asum_i
        double bs = scale * g_bsum[i];
        double ti = scale * g_t[i];                   // normalized t_i
        double xv = (double)outputs[i];
        double yv = (double)event[i];
        g_asum[i] = 0.0; g_bsum[i] = 0.0; g_t[i] = 0.0;   // reset for replay
        s1 += wn * as;           // = N^2 a0
        s2 += wn * bs;           // = N^2 b0
        s3 += wn * as * as;
        s4 += wn * bs * bs;
        s5 += wn * as * bs;
        s6 += wn * ti;           // = T
        s7 += wn * xv;
        s8 += wn * xv * xv;
        s9 += wn * yv;
        s10 += wn * yv * yv;
    }
    s1 = blockReduceD(s1);   s2 = blockReduceD(s2);
    s3 = blockReduceD(s3);   s4 = blockReduceD(s4);
    s5 = blockReduceD(s5);   s6 = blockReduceD(s6);
    s7 = blockReduceD(s7);   s8 = blockReduceD(s8);
    s9 = blockReduceD(s9);   s10 = blockReduceD(s10);

    if (tid == 0) {
        double Nn = (double)n, N2 = Nn * Nn;
        double a0 = s1 / N2, b0 = s2 / N2;
        double SAB = s6 - 2.0 * s5 / Nn + a0 * b0 * N2;
        double SAA = 2.0 * Nn * s8  - 2.0 * s7 * s7 - 2.0 * s3 / Nn + a0 * a0 * N2;
        double SBB = 2.0 * Nn * s10 - 2.0 * s9 * s9 - 2.0 * s4 / Nn + b0 * b0 * N2;
        double disco = SAB / sqrt(SAA * SBB);
        float vals[3];
        vals[0] = bce;
        vals[1] = (float)disco;
        vals[2] = bce + 0.1f * (float)disco;
        int m = out_size < 3 ? out_size : 3;
        for (int i = 0; i < m; ++i) out[i] = vals[i];
        for (int i = 3; i < out_size; ++i) out[i] = 0.0f;
    }
}

// ---------------------------------------------------------------------------
extern "C" void kernel_launch(void* const* d_in, const int* in_sizes, int n_in,
                              void* d_out, int out_size) {
    const float* outputs = (const float*)d_in[0];
    const float* labels  = (const float*)d_in[1];
    const float* event   = (const float*)d_in[2];
    const float* weights = (const float*)d_in[3];
    int n = in_sizes[0];

    dim3 gp(n / (CT * ITEMS), n / CJT);
    kPair<<<gp, CT>>>(outputs, event, weights, n);

    kFinal<<<1, 1024>>>(outputs, labels, event, weights,
                        (float*)d_out, n, out_size);
}

// round 4
// speedup vs baseline: 4.3400x; 4.3400x over previous
#include <cuda_runtime.h>
#include <math.h>

// ---------------------------------------------------------------------------
// BCEDecorrelatedLoss = bce_mean + 0.1 * distance_corr(outputs, event, wnorm)
//
// Validated decomposition (R2/R3, rel_err ~1e-5):
//   raw row sums (linear in raw weights, no preprocessing needed):
//     asum[i]=sum_j w_j|xi-xj| ; bsum[i]=sum_j w_j|yi-yj| ;
//     t[i]   =sum_j w_j|xi-xj||yi-yj|
//   c = N / sum(w);  normalized quantities are c^k * raw sums.
//   With raw sums S1..S10:
//     a0 = c^2 S1 / N^2 ,  b0 = c^2 S2 / N^2
//     S_AB = c^2 S6 - 2 c^3 S5 / N + a0 b0 N^2
//     S_AA = 2N c S8 - 2 (c S7)^2 - 2 c^3 S3 / N + a0^2 N^2
//     S_BB = 2N c S10 - 2 (c S9)^2 - 2 c^3 S4 / N + b0^2 N^2
//     disco = S_AB / sqrt(S_AA S_BB)
//
// FP64 is near-dead on sm_103a -> all double work is spread across the chip
// (kMid: 1 element/thread over 64 blocks) and the 1-thread kFin touches only
// 12 scalars. The O(N^2) kernel kPair is pure fp32 with float row atomics.
// ---------------------------------------------------------------------------

#define MAXN  8192
#define CT    128   // kPair threads per block
#define ITEMS 8     // i-rows per thread
#define CJT   256   // j-tile per block

// zero-initialized at load; kMid re-zeros rows, kFin re-zeros scalars
__device__ float  g_asum[MAXN];
__device__ float  g_bsum[MAXN];
__device__ float  g_t[MAXN];
__device__ double g_s[12];   // 0:sumw 1..10:S1..S10 11:bce_sum

// ---------------------------------------------------------------------------
// kPair: fused O(N^2) pass with RAW weights. grid (n/(CT*ITEMS), n/CJT).
// ---------------------------------------------------------------------------
__global__ void __launch_bounds__(CT) kPair(const float* __restrict__ x,
                                            const float* __restrict__ y,
                                            const float* __restrict__ w,
                                            int n) {
    __shared__ __align__(16) float4 tile[CJT];
    int tid = threadIdx.x;

    // fill j tile: {x_j, y_j, w_j, 0}
    for (int t = tid; t < CJT; t += CT) {
        int j = blockIdx.y * CJT + t;
        tile[t] = make_float4(x[j], y[j], w[j], 0.0f);
    }

    float xi[ITEMS], yi[ITEMS];
    float sa[ITEMS], sb[ITEMS], st[ITEMS];
    int ibase = blockIdx.x * (CT * ITEMS) + tid;
    #pragma unroll
    for (int k = 0; k < ITEMS; ++k) {
        int i = ibase + k * CT;
        xi[k] = x[i]; yi[k] = y[i];
        sa[k] = 0.0f; sb[k] = 0.0f; st[k] = 0.0f;
    }
    __syncthreads();

    #pragma unroll 4
    for (int t = 0; t < CJT; ++t) {
        float4 v = tile[t];            // one LDS.128 serves 8 pairs
        #pragma unroll
        for (int k = 0; k < ITEMS; ++k) {
            float dx  = xi[k] - v.x;
            float dy  = yi[k] - v.y;
            float adx = fabsf(dx);
            float ady = fabsf(dy);
            sa[k] = fmaf(adx, v.z, sa[k]);
            sb[k] = fmaf(ady, v.z, sb[k]);
            st[k] = fmaf(adx * ady, v.z, st[k]);
        }
    }

    #pragma unroll
    for (int k = 0; k < ITEMS; ++k) {
        int i = ibase + k * CT;
        atomicAdd(&g_asum[i], sa[k]);
        atomicAdd(&g_bsum[i], sb[k]);
        atomicAdd(&g_t[i],    st[k]);
    }
}

// ---------------------------------------------------------------------------
// kMid: one element per thread; per-element double products, warp reduce,
// double atomics into g_s. Re-zeros row arrays for graph replay.
// grid: 64 blocks x 128 threads = 8192.
// ---------------------------------------------------------------------------
__global__ void __launch_bounds__(128) kMid(const float* __restrict__ outputs,
                                            const float* __restrict__ labels,
                                            const float* __restrict__ event,
                                            const float* __restrict__ weights,
                                            int n) {
    int i = blockIdx.x * blockDim.x + threadIdx.x;

    float wf = weights[i];
    float xf = outputs[i];
    float yf = event[i];
    float lf = labels[i];
    float as_f = g_asum[i];
    float bs_f = g_bsum[i];
    float tf   = g_t[i];
    g_asum[i] = 0.0f; g_bsum[i] = 0.0f; g_t[i] = 0.0f;   // reset for replay

    // BCE term in fp32 (matches reference's fp32 math)
    float sp  = fmaxf(xf, 0.0f) + log1pf(expf(-fabsf(xf)));
    float bcf = (sp - xf * lf) * wf;

    double w  = (double)wf;
    double as = (double)as_f;
    double bs = (double)bs_f;
    double ti = (double)tf;
    double xv = (double)xf;
    double yv = (double)yf;

    double p[12];
    p[0]  = w;
    p[1]  = w * as;
    p[2]  = w * bs;
    p[3]  = w * as * as;
    p[4]  = w * bs * bs;
    p[5]  = w * as * bs;
    p[6]  = w * ti;
    p[7]  = w * xv;
    p[8]  = w * xv * xv;
    p[9]  = w * yv;
    p[10] = w * yv * yv;
    p[11] = (double)bcf;

    // warp reduce each, lane 0 atomics (32 warps total per scalar)
    #pragma unroll
    for (int s = 0; s < 12; ++s) {
        double v = p[s];
        #pragma unroll
        for (int o = 16; o; o >>= 1) v += __shfl_down_sync(0xffffffffu, v, o);
        if ((threadIdx.x & 31) == 0) atomicAdd(&g_s[s], v);
    }
}

// ---------------------------------------------------------------------------
// kFin (1 thread): assemble disco + bce from 12 scalars; zero them for replay.
// ---------------------------------------------------------------------------
__global__ void kFin(float* __restrict__ out, int n, int out_size) {
    double S0 = g_s[0],  S1 = g_s[1],  S2 = g_s[2],  S3 = g_s[3];
    double S4 = g_s[4],  S5 = g_s[5],  S6 = g_s[6],  S7 = g_s[7];
    double S8 = g_s[8],  S9 = g_s[9],  S10 = g_s[10], SB = g_s[11];
    #pragma unroll
    for (int s = 0; s < 12; ++s) g_s[s] = 0.0;          // reset for replay

    double Nn = (double)n, N2 = Nn * Nn;
    double c  = Nn / S0;
    double c2 = c * c, c3 = c2 * c;

    double a0 = c2 * S1 / N2;
    double b0 = c2 * S2 / N2;
    double SAB = c2 * S6  - 2.0 * c3 * S5 / Nn + a0 * b0 * N2;
    double SAA = 2.0 * Nn * c * S8  - 2.0 * (c * S7) * (c * S7)
               - 2.0 * c3 * S3 / Nn + a0 * a0 * N2;
    double SBB = 2.0 * Nn * c * S10 - 2.0 * (c * S9) * (c * S9)
               - 2.0 * c3 * S4 / Nn + b0 * b0 * N2;
    double disco = SAB / sqrt(SAA * SBB);
    float bce = (float)(SB / Nn);

    float vals[3];
    vals[0] = bce;
    vals[1] = (float)disco;
    vals[2] = bce + 0.1f * (float)disco;
    int m = out_size < 3 ? out_size : 3;
    for (int i = 0; i < m; ++i) out[i] = vals[i];
    for (int i = 3; i < out_size; ++i) out[i] = 0.0f;
}

// ---------------------------------------------------------------------------
extern "C" void kernel_launch(void* const* d_in, const int* in_sizes, int n_in,
                              void* d_out, int out_size) {
    const float* outputs = (const float*)d_in[0];
    const float* labels  = (const float*)d_in[1];
    const float* event   = (const float*)d_in[2];
    const float* weights = (const float*)d_in[3];
    int n = in_sizes[0];

    dim3 gp(n / (CT * ITEMS), n / CJT);
    kPair<<<gp, CT>>>(outputs, event, weights, n);

    kMid<<<n / 128, 128>>>(outputs, labels, event, weights, n);

    kFin<<<1, 1>>>((float*)d_out, n, out_size);
}

// round 5
// speedup vs baseline: 4.8148x; 1.1094x over previous
#include <cuda_runtime.h>
#include <math.h>

// ---------------------------------------------------------------------------
// BCEDecorrelatedLoss = bce_mean + 0.1 * distance_corr(outputs, event, wnorm)
//
// Decomposition (validated R2-R4, rel_err ~1e-5): raw row sums
//   asum[i]=sum_j w_j|xi-xj| ; bsum[i]=sum_j w_j|yi-yj| ; t[i]=sum_j w_j|..||..|
// are linear in raw weights; normalization c=N/sum(w) applied analytically in
// the finalize. Only the row sums need the O(N^2) pass.
//
// R5: pairwise kernel in packed f32x2 using ONLY fma.rn.f32x2 (-> FFMA2),
// abs via 64-bit AND on the ALU pipe, j-pairs read pre-packed from shared.
// 3 fma-slots/pair vs 6 scalar -> targets ~2x on the fma-pipe floor.
// ---------------------------------------------------------------------------

#define MAXN  8192
#define CT    256   // kPair threads per block
#define ITEMS 4     // i-rows per thread
#define CJT   256   // j-tile per block

typedef unsigned long long u64;

__device__ float  g_asum[MAXN];
__device__ float  g_bsum[MAXN];
__device__ float  g_t[MAXN];
__device__ double g_s[12];        // 0:sumw 1..10:S1..S10 11:bce_sum
__device__ unsigned int g_ctr;    // last-block counter (self-resetting)

__device__ __forceinline__ u64 pk2(float lo, float hi) {
    u64 r; asm("mov.b64 %0,{%1,%2};" : "=l"(r) : "f"(lo), "f"(hi)); return r;
}
__device__ __forceinline__ void upk2(u64 v, float& lo, float& hi) {
    asm("mov.b64 {%0,%1},%2;" : "=f"(lo), "=f"(hi) : "l"(v));
}
__device__ __forceinline__ u64 fma2(u64 a, u64 b, u64 c) {
    u64 r; asm("fma.rn.f32x2 %0,%1,%2,%3;" : "=l"(r) : "l"(a), "l"(b), "l"(c));
    return r;
}
#define ABS2(v) ((v) & 0x7FFFFFFF7FFFFFFFULL)

// ---------------------------------------------------------------------------
// kPair: fused O(N^2) pass, packed f32x2. grid (n/(CT*ITEMS), n/CJT).
// ---------------------------------------------------------------------------
__global__ void __launch_bounds__(CT) kPair(const float* __restrict__ x,
                                            const float* __restrict__ y,
                                            const float* __restrict__ w,
                                            int n) {
    __shared__ __align__(8) float snx[CJT];   // -x_j
    __shared__ __align__(8) float sny[CJT];   // -y_j
    __shared__ __align__(8) float swj[CJT];   //  w_j
    int tid = threadIdx.x;

    {
        int j = blockIdx.y * CJT + tid;
        snx[tid] = -x[j];
        sny[tid] = -y[j];
        swj[tid] = w[j];
    }

    const u64 ONE2  = 0x3F8000003F800000ULL;   // {1.0f, 1.0f}
    const u64 ZERO2 = 0ULL;

    u64 xi2[ITEMS], yi2[ITEMS], sa2[ITEMS], sb2[ITEMS], st2[ITEMS];
    int ibase = blockIdx.x * (CT * ITEMS) + tid;
    #pragma unroll
    for (int k = 0; k < ITEMS; ++k) {
        int i = ibase + k * CT;
        float xv = x[i], yv = y[i];
        xi2[k] = pk2(xv, xv);
        yi2[k] = pk2(yv, yv);
        sa2[k] = 0ULL; sb2[k] = 0ULL; st2[k] = 0ULL;
    }
    __syncthreads();

    const u64* nx64 = (const u64*)snx;   // [t] = packed (-x_{2t}, -x_{2t+1})
    const u64* ny64 = (const u64*)sny;
    const u64* w64  = (const u64*)swj;

    #pragma unroll 4
    for (int t = 0; t < CJT / 2; ++t) {
        u64 nxq = nx64[t];               // LDS.64 broadcast, conflict-free
        u64 nyq = ny64[t];
        u64 wq  = w64[t];
        #pragma unroll
        for (int k = 0; k < ITEMS; ++k) {
            u64 dx  = fma2(xi2[k], ONE2, nxq);     // (xi-xj0, xi-xj1)
            u64 dy  = fma2(yi2[k], ONE2, nyq);
            u64 adx = ABS2(dx);                    // LOP3 (ALU pipe)
            u64 ady = ABS2(dy);
            sa2[k] = fma2(adx, wq, sa2[k]);
            sb2[k] = fma2(ady, wq, sb2[k]);
            u64 pr = fma2(adx, ady, ZERO2);
            st2[k] = fma2(pr, wq, st2[k]);
        }
    }

    #pragma unroll
    for (int k = 0; k < ITEMS; ++k) {
        int i = ibase + k * CT;
        float lo, hi;
        upk2(sa2[k], lo, hi); atomicAdd(&g_asum[i], lo + hi);
        upk2(sb2[k], lo, hi); atomicAdd(&g_bsum[i], lo + hi);
        upk2(st2[k], lo, hi); atomicAdd(&g_t[i],    lo + hi);
    }
}

// ---------------------------------------------------------------------------
// kMid: one element/thread; double products -> warp reduce -> double atomics.
// Re-zeros row arrays. Last block finalizes (counter-elected) and writes out.
// grid: n/128 blocks x 128 threads.
// ---------------------------------------------------------------------------
__global__ void __launch_bounds__(128) kMid(const float* __restrict__ outputs,
                                            const float* __restrict__ labels,
                                            const float* __restrict__ event,
                                            const float* __restrict__ weights,
                                            float* __restrict__ out,
                                            int n, int out_size) {
    int i = blockIdx.x * blockDim.x + threadIdx.x;

    float wf = weights[i];
    float xf = outputs[i];
    float yf = event[i];
    float lf = labels[i];
    float as_f = g_asum[i];
    float bs_f = g_bsum[i];
    float tf   = g_t[i];
    g_asum[i] = 0.0f; g_bsum[i] = 0.0f; g_t[i] = 0.0f;   // reset for replay

    float sp  = fmaxf(xf, 0.0f) + log1pf(expf(-fabsf(xf)));   // logaddexp(0,x)
    float bcf = (sp - xf * lf) * wf;

    double wd = (double)wf;
    double as = (double)as_f;
    double bs = (double)bs_f;
    double ti = (double)tf;
    double xv = (double)xf;
    double yv = (double)yf;

    double p[12];
    p[0]  = wd;
    p[1]  = wd * as;
    p[2]  = wd * bs;
    p[3]  = wd * as * as;
    p[4]  = wd * bs * bs;
    p[5]  = wd * as * bs;
    p[6]  = wd * ti;
    p[7]  = wd * xv;
    p[8]  = wd * xv * xv;
    p[9]  = wd * yv;
    p[10] = wd * yv * yv;
    p[11] = (double)bcf;

    #pragma unroll
    for (int s = 0; s < 12; ++s) {
        double v = p[s];
        #pragma unroll
        for (int o = 16; o; o >>= 1) v += __shfl_down_sync(0xffffffffu, v, o);
        if ((threadIdx.x & 31) == 0) atomicAdd(&g_s[s], v);
    }

    // ---- last-block finalize -------------------------------------------------
    __shared__ bool is_last;
    __threadfence();
    if (threadIdx.x == 0) {
        unsigned int c = atomicAdd(&g_ctr, 1u);
        is_last = (c == gridDim.x - 1);
    }
    __syncthreads();
    if (is_last && threadIdx.x == 0) {
        g_ctr = 0;                                   // reset for replay
        double S0 = g_s[0],  S1 = g_s[1],  S2 = g_s[2],  S3 = g_s[3];
        double S4 = g_s[4],  S5 = g_s[5],  S6 = g_s[6],  S7 = g_s[7];
        double S8 = g_s[8],  S9 = g_s[9],  S10 = g_s[10], SBc = g_s[11];
        #pragma unroll
        for (int s = 0; s < 12; ++s) g_s[s] = 0.0;   // reset for replay

        double Nn = (double)n, N2 = Nn * Nn;
        double c2 = (Nn / S0) * (Nn / S0);
        double c1 = Nn / S0;
        double c3 = c2 * c1;

        double a0 = c2 * S1 / N2;
        double b0 = c2 * S2 / N2;
        double SAB = c2 * S6 - 2.0 * c3 * S5 / Nn + a0 * b0 * N2;
        double SAA = 2.0 * Nn * c1 * S8  - 2.0 * (c1 * S7) * (c1 * S7)
                   - 2.0 * c3 * S3 / Nn + a0 * a0 * N2;
        double SBB = 2.0 * Nn * c1 * S10 - 2.0 * (c1 * S9) * (c1 * S9)
                   - 2.0 * c3 * S4 / Nn + b0 * b0 * N2;
        double disco = SAB / sqrt(SAA * SBB);
        float bce = (float)(SBc / Nn);

        float vals[3];
        vals[0] = bce;
        vals[1] = (float)disco;
        vals[2] = bce + 0.1f * (float)disco;
        int m = out_size < 3 ? out_size : 3;
        for (int q = 0; q < m; ++q) out[q] = vals[q];
        for (int q = 3; q < out_size; ++q) out[q] = 0.0f;
    }
}

// ---------------------------------------------------------------------------
extern "C" void kernel_launch(void* const* d_in, const int* in_sizes, int n_in,
                              void* d_out, int out_size) {
    const float* outputs = (const float*)d_in[0];
    const float* labels  = (const float*)d_in[1];
    const float* event   = (const float*)d_in[2];
    const float* weights = (const float*)d_in[3];
    int n = in_sizes[0];

    dim3 gp(n / (CT * ITEMS), n / CJT);
    kPair<<<gp, CT>>>(outputs, event, weights, n);

    kMid<<<n / 128, 128>>>(outputs, labels, event, weights,
                           (float*)d_out, n, out_size);
}